// round 14
// baseline (speedup 1.0000x reference)
#include <cuda_runtime.h>
#include <math.h>

#define NN 100000
#define NE 1600000
#define NG 512
#define NB_SCAN 391            // ceil(NN/256)

typedef unsigned long long ull;

// ---------------- device scratch ----------------
__device__ int   g_is64;
__device__ float g_bufA[NN * 64];
__device__ float g_bufB[NN * 64];
__device__ float g_agg [NN * 64];
__device__ float g_sums[NG * 16];
__device__ float g_cnts[NG];
// CSR scratch
__device__ int g_deg [NN];
__device__ int g_excl[NN];
__device__ int g_part[512];
__device__ int g_rptr[NN + 1];
__device__ int g_cur [NN];
__device__ int g_csrc[NE];

// ---------------- dynamic smem layout for k_conv (MMA path) ----------------
#define SM_TMEM 0
#define SM_MBAR 8
#define SM_BIAS 16
#define SM_A    1024                 // 128x128 tf32, blocked SW128 atoms: 65536 B
#define SM_B    (1024 + 65536)       // 64x128 tf32: 32768 B
#define SM_TOTAL (SM_B + 32768)      // 99328 B

#define TILES_PER_CTA 4

// idesc: d=F32(1<<4), a=TF32(2<<7), b=TF32(2<<10), N=64 (8<<17), M=128 (8<<24)
#define IDESC_TF32 ((1u<<4)|(2u<<7)|(2u<<10)|(8u<<17)|(8u<<24))

static __device__ __forceinline__ ull fma2(ull a, ull b, ull c) {
    ull d;
    asm("fma.rn.f32x2 %0, %1, %2, %3;" : "=l"(d) : "l"(a), "l"(b), "l"(c));
    return d;
}
static __device__ __forceinline__ unsigned smem_u32(const void* p) {
    unsigned a;
    asm("{ .reg .u64 t; cvta.to.shared.u64 t, %1; cvt.u32.u64 %0, t; }" : "=r"(a) : "l"(p));
    return a;
}
static __device__ __forceinline__ unsigned f2tf32(float f) {
    unsigned r;
    asm("cvt.rna.satfinite.tf32.f32 %0, %1;" : "=r"(r) : "f"(f));
    return r;
}
static __device__ __forceinline__ int a_off(int node, int kcol) {
    int b = (((node >> 3) + (kcol >> 5) * 16) << 10) + ((node & 7) << 7) + ((kcol & 31) << 2);
    return b ^ ((b >> 3) & 0x70);
}
static __device__ __forceinline__ int b_off(int j, int k) {
    int b = (((j >> 3) + (k >> 5) * 8) << 10) + ((j & 7) << 7) + ((k & 31) << 2);
    return b ^ ((b >> 3) & 0x70);
}
#define DESC_BASE ((2ULL<<61)|(1ULL<<46)|(64ULL<<32)|(1ULL<<16))

// ---------------- dtype detection ----------------
__global__ void k_detect(const unsigned int* __restrict__ ei) {
    if (threadIdx.x == 0) {
        int is64 = 1;
        #pragma unroll 1
        for (int i = 1; i < 128; i += 2) {
            if (ei[i] != 0u) { is64 = 0; break; }
        }
        g_is64 = is64;
    }
}

// ---------------- CSR build ----------------
__global__ void k_zdeg() {
    int i = blockIdx.x * 256 + threadIdx.x;
    if (i < NN) g_deg[i] = 0;
}
__global__ void k_hist(const void* __restrict__ ei_) {
    int e = blockIdx.x * 256 + threadIdx.x;
    int d;
    if (g_is64) d = (int)((const long long*)ei_)[NE + e];
    else        d = ((const int*)ei_)[NE + e];
    atomicAdd(&g_deg[d], 1);
}
__global__ void k_scan1() {
    __shared__ int s[256];
    int t = threadIdx.x;
    int i = blockIdx.x * 256 + t;
    int v = (i < NN) ? g_deg[i] : 0;
    s[t] = v;
    __syncthreads();
    #pragma unroll
    for (int ofs = 1; ofs < 256; ofs <<= 1) {
        int add = (t >= ofs) ? s[t - ofs] : 0;
        __syncthreads();
        s[t] += add;
        __syncthreads();
    }
    if (i < NN) g_excl[i] = s[t] - v;
    if (t == 255) g_part[blockIdx.x] = s[t];
}
__global__ void k_scan2() {
    __shared__ int s[512];
    int t = threadIdx.x;
    int v = (t < NB_SCAN) ? g_part[t] : 0;
    s[t] = v;
    __syncthreads();
    #pragma unroll
    for (int ofs = 1; ofs < 512; ofs <<= 1) {
        int add = (t >= ofs) ? s[t - ofs] : 0;
        __syncthreads();
        s[t] += add;
        __syncthreads();
    }
    if (t < NB_SCAN) g_part[t] = s[t] - v;
    if (t == 0) g_rptr[NN] = NE;
}
__global__ void k_scan3() {
    int i = blockIdx.x * 256 + threadIdx.x;
    if (i < NN) {
        int r = g_excl[i] + g_part[i >> 8];
        g_rptr[i] = r;
        g_cur[i] = r;
    }
}
__global__ void k_permute(const void* __restrict__ ei_) {
    int e = blockIdx.x * 256 + threadIdx.x;
    int s, d;
    if (g_is64) {
        const long long* E = (const long long*)ei_;
        s = (int)E[e]; d = (int)E[NE + e];
    } else {
        const int* E = (const int*)ei_;
        s = E[e]; d = E[NE + e];
    }
    int pos = atomicAdd(&g_cur[d], 1);
    g_csrc[pos] = s;
}

// ------- h0 = x @ W0 + b0; zero pooled accumulators (atomics happen later) -------
__global__ void __launch_bounds__(256) k_lin0(const float* __restrict__ x,
                                              const float* __restrict__ W0,
                                              const float* __restrict__ b0) {
    __shared__ float sW[11 * 64];
    __shared__ float sB[64];
    int t = threadIdx.x;
    for (int i = t; i < 11 * 64; i += 256) sW[i] = W0[i];
    if (t < 64) sB[t] = b0[t];
    __syncthreads();

    int gid = blockIdx.x * 256 + t;
    int n = gid >> 6, j = gid & 63;
    const float* xr = x + n * 11;
    float acc = sB[j];
    #pragma unroll
    for (int k = 0; k < 11; k++) acc += xr[k] * sW[k * 64 + j];
    g_bufA[gid] = acc;
    if (gid < NG * 16) g_sums[gid] = 0.0f;
    if (gid < NG)      g_cnts[gid] = 0.0f;
}

// ---------------- pull gather: agg[d] = sum_{e: dst=d} h[src[e]] ----------------
__global__ void __launch_bounds__(256) k_gather(int in_sel) {
    const float4* __restrict__ h = (const float4*)(in_sel ? g_bufB : g_bufA);
    int grp = blockIdx.x * 16 + (threadIdx.x >> 4);   // 6250*16 = NN exact
    int c = threadIdx.x & 15;
    int r0 = g_rptr[grp], r1 = g_rptr[grp + 1];
    float4 acc = make_float4(0.f, 0.f, 0.f, 0.f);
    int i = r0;
    for (; i + 2 <= r1; i += 2) {
        int s0 = g_csrc[i], s1 = g_csrc[i + 1];
        float4 v0 = h[s0 * 16 + c];
        float4 v1 = h[s1 * 16 + c];
        acc.x += v0.x; acc.y += v0.y; acc.z += v0.z; acc.w += v0.w;
        acc.x += v1.x; acc.y += v1.y; acc.z += v1.z; acc.w += v1.w;
    }
    if (i < r1) {
        int s0 = g_csrc[i];
        float4 v0 = h[s0 * 16 + c];
        acc.x += v0.x; acc.y += v0.y; acc.z += v0.z; acc.w += v0.w;
    }
    ((float4*)g_agg)[grp * 16 + c] = acc;
}

// -------- conv: h_out = tanh(agg @ Wrel + brel + h_in @ Wroot) --------------------
// 4 tiles of 128 nodes per CTA: weights + TMEM alloc amortized across tiles.
__global__ void __launch_bounds__(256) k_conv(int in_sel,
                                              const float* __restrict__ Wrel,
                                              const float* __restrict__ brel,
                                              const float* __restrict__ Wroot,
                                              int out_sel) {
    extern __shared__ __align__(16) char sm_[];
    const float* __restrict__ hin  = in_sel  ? g_bufB : g_bufA;
    float* __restrict__       hout = out_sel ? g_bufB : g_bufA;
    int t = threadIdx.x;

#if defined(__CUDA_ARCH_FEAT_SM103_ALL)
    int wid = t >> 5, lid = t & 31;
    unsigned smb = smem_u32(sm_);

    if (wid == 0) {
        asm volatile("tcgen05.alloc.cta_group::1.sync.aligned.shared::cta.b32 [%0], %1;"
                     :: "r"(smb + SM_TMEM), "r"(128u) : "memory");
        asm volatile("tcgen05.relinquish_alloc_permit.cta_group::1.sync.aligned;");
    }
    if (t == 0)
        asm volatile("mbarrier.init.shared.b64 [%0], %1;" :: "r"(smb + SM_MBAR), "r"(1u) : "memory");
    if (t < 64) ((float*)(sm_ + SM_BIAS))[t] = brel[t];

    // ---- weights: loaded ONCE per CTA ----
    #pragma unroll
    for (int i = 0; i < 32; i++) {
        int idx = t + i * 256;
        int k = idx >> 6, j = idx & 63;
        float w = (k < 64) ? Wrel[k * 64 + j] : Wroot[(k - 64) * 64 + j];
        *(unsigned*)(sm_ + SM_B + b_off(j, k)) = f2tf32(w);
    }
    __syncthreads();

    unsigned tmem;
    asm volatile("ld.shared.b32 %0, [%1];" : "=r"(tmem) : "r"(smb + SM_TMEM));

    float* sOut = (float*)(sm_ + SM_A);
    const float* sBias = (float*)(sm_ + SM_BIAS);

    for (int ti = 0; ti < TILES_PER_CTA; ti++) {
        int n0 = (blockIdx.x * TILES_PER_CTA + ti) * 128;
        if (n0 >= NN) break;
        int valid = NN - n0; if (valid > 128) valid = 128;

        // ---- load A = [agg | hin] as tf32 (SM_A also serves as prior tile's sOut;
        //      the __syncthreads at the end of the previous iteration protects it) ----
        #pragma unroll
        for (int i = 0; i < 16; i++) {
            int idx = t + i * 256;
            int node = idx >> 5, q = idx & 31;
            if (node < valid) {
                float4 v = (q < 16) ? *(const float4*)&g_agg[(n0 + node) * 64 + q * 4]
                                    : *(const float4*)&hin [(n0 + node) * 64 + (q - 16) * 4];
                uint4 u = make_uint4(f2tf32(v.x), f2tf32(v.y), f2tf32(v.z), f2tf32(v.w));
                *(uint4*)(sm_ + SM_A + a_off(node, q * 4)) = u;
            }
        }
        asm volatile("fence.proxy.async.shared::cta;" ::: "memory");
        __syncthreads();

        if (wid == 0) {
            asm volatile("tcgen05.fence::after_thread_sync;" ::: "memory");
            unsigned ep;
            asm volatile("{ .reg .pred p; elect.sync _|p, 0xFFFFFFFF; selp.b32 %0, 1, 0, p; }" : "=r"(ep));
            if (ep) {
                ull da = DESC_BASE | (((ull)((smb + SM_A) >> 4)) & 0x3FFF);
                ull db = DESC_BASE | (((ull)((smb + SM_B) >> 4)) & 0x3FFF);
                #pragma unroll
                for (int s = 0; s < 16; s++) {
                    int ac = s >> 2, kk = s & 3;
                    unsigned en = (s > 0);
                    asm volatile("{\n\t.reg .pred p;\n\tsetp.ne.u32 p, %4, 0;\n\t"
                                 "tcgen05.mma.cta_group::1.kind::tf32 [%0], %1, %2, %3, p;\n\t}"
                                 :: "r"(tmem), "l"(da + ac * 1024 + kk * 2),
                                    "l"(db + ac * 512 + kk * 2), "r"(IDESC_TF32), "r"(en) : "memory");
                }
                asm volatile("tcgen05.commit.cta_group::1.mbarrier::arrive::one.shared::cluster.b64 [%0];"
                             :: "r"(smb + SM_MBAR) : "memory");
            }
        }

        { // wait for MMA; phase parity flips each tile
            unsigned mb = smb + SM_MBAR, par = (unsigned)(ti & 1), done;
            asm volatile("{\n\t.reg .pred p;\n\t"
                         "mbarrier.try_wait.parity.acquire.cta.shared::cta.b64 p, [%1], %2;\n\t"
                         "selp.b32 %0, 1, 0, p;\n\t}" : "=r"(done) : "r"(mb), "r"(par) : "memory");
            if (!done) {
                asm volatile("{\n\t.reg .pred P1;\n\t"
                             "W%=:\n\t"
                             "mbarrier.try_wait.parity.acquire.cta.shared::cta.b64 P1, [%0], %1, 0x989680;\n\t"
                             "@P1 bra.uni D%=;\n\t"
                             "bra.uni W%=;\n\t"
                             "D%=:\n\t}" :: "r"(mb), "r"(par) : "memory");
            }
        }
        asm volatile("tcgen05.fence::after_thread_sync;" ::: "memory");

        // ---- epilogue: warps 0-3 read D, tanh, stage to smem (reuses SM_A) ----
        if (wid < 4) {
            unsigned r[64];
            asm volatile("tcgen05.ld.sync.aligned.32x32b.x32.b32 "
                "{%0,%1,%2,%3,%4,%5,%6,%7,%8,%9,%10,%11,%12,%13,%14,%15,"
                "%16,%17,%18,%19,%20,%21,%22,%23,%24,%25,%26,%27,%28,%29,%30,%31}, [%32];"
                : "=r"(r[0]),"=r"(r[1]),"=r"(r[2]),"=r"(r[3]),"=r"(r[4]),"=r"(r[5]),"=r"(r[6]),"=r"(r[7]),
                  "=r"(r[8]),"=r"(r[9]),"=r"(r[10]),"=r"(r[11]),"=r"(r[12]),"=r"(r[13]),"=r"(r[14]),"=r"(r[15]),
                  "=r"(r[16]),"=r"(r[17]),"=r"(r[18]),"=r"(r[19]),"=r"(r[20]),"=r"(r[21]),"=r"(r[22]),"=r"(r[23]),
                  "=r"(r[24]),"=r"(r[25]),"=r"(r[26]),"=r"(r[27]),"=r"(r[28]),"=r"(r[29]),"=r"(r[30]),"=r"(r[31])
                : "r"(tmem));
            asm volatile("tcgen05.ld.sync.aligned.32x32b.x32.b32 "
                "{%0,%1,%2,%3,%4,%5,%6,%7,%8,%9,%10,%11,%12,%13,%14,%15,"
                "%16,%17,%18,%19,%20,%21,%22,%23,%24,%25,%26,%27,%28,%29,%30,%31}, [%32];"
                : "=r"(r[32]),"=r"(r[33]),"=r"(r[34]),"=r"(r[35]),"=r"(r[36]),"=r"(r[37]),"=r"(r[38]),"=r"(r[39]),
                  "=r"(r[40]),"=r"(r[41]),"=r"(r[42]),"=r"(r[43]),"=r"(r[44]),"=r"(r[45]),"=r"(r[46]),"=r"(r[47]),
                  "=r"(r[48]),"=r"(r[49]),"=r"(r[50]),"=r"(r[51]),"=r"(r[52]),"=r"(r[53]),"=r"(r[54]),"=r"(r[55]),
                  "=r"(r[56]),"=r"(r[57]),"=r"(r[58]),"=r"(r[59]),"=r"(r[60]),"=r"(r[61]),"=r"(r[62]),"=r"(r[63])
                : "r"(tmem + 32));
            asm volatile("tcgen05.wait::ld.sync.aligned;" ::: "memory");

            int node = wid * 32 + lid;
            if (node < valid) {
                #pragma unroll
                for (int c = 0; c < 64; c += 2) {
                    float2 o;
                    o.x = tanhf(__uint_as_float(r[c])     + sBias[c]);
                    o.y = tanhf(__uint_as_float(r[c + 1]) + sBias[c + 1]);
                    *(float2*)&sOut[node * 66 + c] = o;
                }
            }
        }
        __syncthreads();

        // ---- coalesced store ----
        #pragma unroll
        for (int i = 0; i < 8; i++) {
            int off = (t + i * 256) * 4;
            if (off < valid * 64) {
                int n = off >> 6, k = off & 63;
                const float* ps = &sOut[n * 66 + k];
                *(float4*)&hout[n0 * 64 + off] = make_float4(ps[0], ps[1], ps[2], ps[3]);
            }
        }
        __syncthreads();   // sOut reads done before next tile overwrites SM_A
    }

    if (t < 32) {
        if (t == 0)
            asm volatile("mbarrier.inval.shared.b64 [%0];" :: "r"(smb + SM_MBAR) : "memory");
        asm volatile("tcgen05.dealloc.cta_group::1.sync.aligned.b32 %0, %1;" :: "r"(tmem), "r"(128u));
    }
#else
    // ---------- scalar f32x2 fallback (non-103a PTX pass) ----------
    float* sA   = (float*)sm_;
    float* sH   = sA   + 64 * 66;
    float* sWrT = sH   + 64 * 66;
    float* sWoT = sWrT + 64 * 66;
    float* sB   = sWoT + 64 * 66;

    #pragma unroll
    for (int i = 0; i < 4; i++) {
        int idx4 = t + i * 256;
        float4 wr = ((const float4*)Wrel)[idx4];
        float4 wo = ((const float4*)Wroot)[idx4];
        int k = idx4 >> 4;
        int j = (idx4 & 15) * 4;
        sWrT[(j + 0) * 66 + k] = wr.x; sWrT[(j + 1) * 66 + k] = wr.y;
        sWrT[(j + 2) * 66 + k] = wr.z; sWrT[(j + 3) * 66 + k] = wr.w;
        sWoT[(j + 0) * 66 + k] = wo.x; sWoT[(j + 1) * 66 + k] = wo.y;
        sWoT[(j + 2) * 66 + k] = wo.z; sWoT[(j + 3) * 66 + k] = wo.w;
    }
    if (t < 64) sB[t] = brel[t];

    for (int ti = 0; ti < TILES_PER_CTA; ti++) {
        int base = (blockIdx.x * TILES_PER_CTA + ti) * 128;
        if (base >= NN) break;
        for (int half = 0; half < 2; half++) {
            int m0 = base + half * 64;
            if (m0 >= NN) break;
            int vlim = (NN - m0) * 64; if (vlim > 4096) vlim = 4096;
            __syncthreads();
            #pragma unroll
            for (int i = 0; i < 4; i++) {
                int off = (t + i * 256) * 4;
                int n = off >> 6, k = off & 63;
                float4 va, vh;
                if (off < vlim) {
                    va = *(const float4*)&g_agg[m0 * 64 + off];
                    vh = *(const float4*)&hin [m0 * 64 + off];
                } else { va = make_float4(0.f,0.f,0.f,0.f); vh = va; }
                float* pa = &sA[n * 66 + k];
                float* ph = &sH[n * 66 + k];
                pa[0] = va.x; pa[1] = va.y; pa[2] = va.z; pa[3] = va.w;
                ph[0] = vh.x; ph[1] = vh.y; ph[2] = vh.z; ph[3] = vh.w;
            }
            __syncthreads();

            int jq = t & 15;
            int nb = (t >> 4) * 4;
            ull acc[4][4];
            #pragma unroll
            for (int n = 0; n < 4; n++)
                #pragma unroll
                for (int c = 0; c < 4; c++) acc[n][c] = 0ull;

            const float* pa = &sA[nb * 66];
            const float* ph = &sH[nb * 66];
            const float* pwr = &sWrT[jq * 66];
            const float* pwo = &sWoT[jq * 66];

            #pragma unroll 2
            for (int k = 0; k < 64; k += 2) {
                ull wr[4], wo[4], a[4], h[4];
                #pragma unroll
                for (int c = 0; c < 4; c++) {
                    wr[c] = *(const ull*)(pwr + c * 16 * 66 + k);
                    wo[c] = *(const ull*)(pwo + c * 16 * 66 + k);
                }
                #pragma unroll
                for (int n = 0; n < 4; n++) {
                    a[n] = *(const ull*)(pa + n * 66 + k);
                    h[n] = *(const ull*)(ph + n * 66 + k);
                }
                #pragma unroll
                for (int n = 0; n < 4; n++) {
                    #pragma unroll
                    for (int c = 0; c < 4; c++) {
                        acc[n][c] = fma2(a[n], wr[c], acc[n][c]);
                        acc[n][c] = fma2(h[n], wo[c], acc[n][c]);
                    }
                }
            }

            __syncthreads();
            #pragma unroll
            for (int n = 0; n < 4; n++) {
                #pragma unroll
                for (int c = 0; c < 4; c++) {
                    int col = jq + 16 * c;
                    float2 p = *(float2*)&acc[n][c];
                    sA[(nb + n) * 66 + col] = tanhf(p.x + p.y + sB[col]);
                }
            }
            __syncthreads();
            #pragma unroll
            for (int i = 0; i < 4; i++) {
                int off = (t + i * 256) * 4;
                if (off < vlim) {
                    int n = off >> 6, k = off & 63;
                    const float* ps = &sA[n * 66 + k];
                    *(float4*)&hout[m0 * 64 + off] = make_float4(ps[0], ps[1], ps[2], ps[3]);
                }
            }
        }
    }
#endif
}

// -------- h3 = tanh(h2 @ W3 + b3) + pooled sums via smem-staged rows --------
__global__ void __launch_bounds__(256) k_lin3pool(const void* __restrict__ bat_,
                                                  const float* __restrict__ W3,
                                                  const float* __restrict__ b3) {
    __shared__ float sW[64 * 16];
    __shared__ float sB[16];
    __shared__ float sRow[16 * 65];
    int t = threadIdx.x;
    for (int i = t; i < 64 * 16; i += 256) sW[i] = W3[i];
    if (t < 16) sB[t] = b3[t];

    int n0 = blockIdx.x * 16;                 // 6250 blocks, exact
    {
        int off = t * 4;                      // 16 rows x 64 floats = 256 float4
        int n = off >> 6, k = off & 63;
        float4 v = *(const float4*)&g_bufA[(n0 + n) * 64 + k];
        float* p = &sRow[n * 65 + k];
        p[0] = v.x; p[1] = v.y; p[2] = v.z; p[3] = v.w;
    }
    __syncthreads();

    int n = t >> 4, j = t & 15;
    const float* hr = &sRow[n * 65];
    float acc = sB[j];
    #pragma unroll
    for (int k = 0; k < 64; k++) acc += hr[k] * sW[k * 16 + j];
    float v = tanhf(acc);
    int node = n0 + n;
    int g;
    if (g_is64) g = (int)((const long long*)bat_)[node];
    else        g = ((const int*)bat_)[node];
    atomicAdd(&g_sums[g * 16 + j], v);
    if (j == 0) atomicAdd(&g_cnts[g], 1.0f);
}

// ---------------- mean pool + NormalParamExtractor ------------------------------
__global__ void k_final(float* __restrict__ out) {
    int t = blockIdx.x * blockDim.x + threadIdx.x;
    if (t >= NG * 16) return;
    int g = t >> 4, j = t & 15;
    float m = g_sums[t] / fmaxf(g_cnts[g], 1.0f);
    if (j < 8) {
        out[g * 8 + j] = m;
    } else {
        float s = m + 0.54132485461292192f;
        float sp = (s > 20.0f) ? s : log1pf(expf(s));
        out[NG * 8 + g * 8 + (j - 8)] = fmaxf(sp, 1e-4f);
    }
}

// ---------------- launch ---------------------------------------------------------
extern "C" void kernel_launch(void* const* d_in, const int* in_sizes, int n_in,
                              void* d_out, int out_size) {
    const float* x     = (const float*)d_in[0];
    const void*  ei    = d_in[1];
    const void*  bat   = d_in[2];
    const float* W0    = (const float*)d_in[3];
    const float* b0    = (const float*)d_in[4];
    const float* Wrel1 = (const float*)d_in[5];
    const float* brel1 = (const float*)d_in[6];
    const float* Wroot1= (const float*)d_in[7];
    const float* Wrel2 = (const float*)d_in[8];
    const float* brel2 = (const float*)d_in[9];
    const float* Wroot2= (const float*)d_in[10];
    const float* W3    = (const float*)d_in[11];
    const float* b3    = (const float*)d_in[12];
    float* out = (float*)d_out;

    cudaFuncSetAttribute(k_conv, cudaFuncAttributeMaxDynamicSharedMemorySize, SM_TOTAL);

    // --- CSR build (indices only; reused by both layers) ---
    k_detect<<<1, 32>>>((const unsigned int*)ei);
    k_zdeg<<<NB_SCAN, 256>>>();
    k_hist<<<NE / 256, 256>>>(ei);
    k_scan1<<<NB_SCAN, 256>>>();
    k_scan2<<<1, 512>>>();
    k_scan3<<<NB_SCAN, 256>>>();
    k_permute<<<NE / 256, 256>>>(ei);

    k_lin0<<<NN * 64 / 256, 256>>>(x, W0, b0);          // h0 -> bufA; sums/cnts = 0

    const int NT = (NN + 127) / 128;                    // 782 tiles
    const int CONV_GRID = (NT + TILES_PER_CTA - 1) / TILES_PER_CTA;   // 196
    k_gather<<<NN / 16, 256>>>(0);                      // agg = sum h0[src]
    k_conv<<<CONV_GRID, 256, SM_TOTAL>>>(0, Wrel1, brel1, Wroot1, 1); // h1 -> bufB

    k_gather<<<NN / 16, 256>>>(1);                      // agg = sum h1[src]
    k_conv<<<CONV_GRID, 256, SM_TOTAL>>>(1, Wrel2, brel2, Wroot2, 0); // h2 -> bufA

    k_lin3pool<<<NN / 16, 256>>>(bat, W3, b3);
    k_final<<<(NG * 16 + 255) / 256, 256>>>(out);
}

// round 15
// speedup vs baseline: 1.0978x; 1.0978x over previous
#include <cuda_runtime.h>
#include <math.h>

#define NN 100000
#define NE 1600000
#define NG 512
#define NB_SCAN 391            // ceil(NN/256)

typedef unsigned long long ull;

// ---------------- device scratch ----------------
__device__ int   g_is64;
__device__ float g_bufA[NN * 64];
__device__ float g_bufB[NN * 64];
__device__ float g_agg [NN * 64];
__device__ float g_sums[NG * 16];
__device__ float g_cnts[NG];
// CSR scratch
__device__ int g_deg [NN];
__device__ int g_excl[NN];
__device__ int g_part[512];
__device__ int g_rptr[NN + 1];
__device__ int g_cur [NN];
__device__ int g_csrc[NE];

// ---------------- dynamic smem layout for k_conv (MMA path) ----------------
#define SM_TMEM 0
#define SM_MBAR 8
#define SM_BIAS 16
#define SM_A    1024                 // 128x128 tf32, blocked SW128 atoms: 65536 B
#define SM_B    (1024 + 65536)       // 64x128 tf32: 32768 B
#define SM_TOTAL (SM_B + 32768)      // 99328 B

// idesc: d=F32(1<<4), a=TF32(2<<7), b=TF32(2<<10), N=64 (8<<17), M=128 (8<<24)
#define IDESC_TF32 ((1u<<4)|(2u<<7)|(2u<<10)|(8u<<17)|(8u<<24))

static __device__ __forceinline__ ull fma2(ull a, ull b, ull c) {
    ull d;
    asm("fma.rn.f32x2 %0, %1, %2, %3;" : "=l"(d) : "l"(a), "l"(b), "l"(c));
    return d;
}
static __device__ __forceinline__ unsigned smem_u32(const void* p) {
    unsigned a;
    asm("{ .reg .u64 t; cvta.to.shared.u64 t, %1; cvt.u32.u64 %0, t; }" : "=r"(a) : "l"(p));
    return a;
}
static __device__ __forceinline__ unsigned f2tf32(float f) {
    unsigned r;
    asm("cvt.rna.satfinite.tf32.f32 %0, %1;" : "=r"(r) : "f"(f));
    return r;
}
static __device__ __forceinline__ int a_off(int node, int kcol) {
    int b = (((node >> 3) + (kcol >> 5) * 16) << 10) + ((node & 7) << 7) + ((kcol & 31) << 2);
    return b ^ ((b >> 3) & 0x70);
}
static __device__ __forceinline__ int b_off(int j, int k) {
    int b = (((j >> 3) + (k >> 5) * 8) << 10) + ((j & 7) << 7) + ((k & 31) << 2);
    return b ^ ((b >> 3) & 0x70);
}
#define DESC_BASE ((2ULL<<61)|(1ULL<<46)|(64ULL<<32)|(1ULL<<16))

// ---------------- dtype detection ----------------
__global__ void k_detect(const unsigned int* __restrict__ ei) {
    if (threadIdx.x == 0) {
        int is64 = 1;
        #pragma unroll 1
        for (int i = 1; i < 128; i += 2) {
            if (ei[i] != 0u) { is64 = 0; break; }
        }
        g_is64 = is64;
    }
}

// ---------------- CSR build ----------------
__global__ void k_zdeg() {
    int i = blockIdx.x * 256 + threadIdx.x;
    if (i < NN) g_deg[i] = 0;
}
__global__ void k_hist(const void* __restrict__ ei_) {
    int e = blockIdx.x * 256 + threadIdx.x;
    int d;
    if (g_is64) d = (int)((const long long*)ei_)[NE + e];
    else        d = ((const int*)ei_)[NE + e];
    atomicAdd(&g_deg[d], 1);
}
__global__ void k_scan1() {
    __shared__ int s[256];
    int t = threadIdx.x;
    int i = blockIdx.x * 256 + t;
    int v = (i < NN) ? g_deg[i] : 0;
    s[t] = v;
    __syncthreads();
    #pragma unroll
    for (int ofs = 1; ofs < 256; ofs <<= 1) {
        int add = (t >= ofs) ? s[t - ofs] : 0;
        __syncthreads();
        s[t] += add;
        __syncthreads();
    }
    if (i < NN) g_excl[i] = s[t] - v;
    if (t == 255) g_part[blockIdx.x] = s[t];
}
__global__ void k_scan2() {
    __shared__ int s[512];
    int t = threadIdx.x;
    int v = (t < NB_SCAN) ? g_part[t] : 0;
    s[t] = v;
    __syncthreads();
    #pragma unroll
    for (int ofs = 1; ofs < 512; ofs <<= 1) {
        int add = (t >= ofs) ? s[t - ofs] : 0;
        __syncthreads();
        s[t] += add;
        __syncthreads();
    }
    if (t < NB_SCAN) g_part[t] = s[t] - v;
    if (t == 0) g_rptr[NN] = NE;
}
__global__ void k_scan3() {
    int i = blockIdx.x * 256 + threadIdx.x;
    if (i < NN) {
        int r = g_excl[i] + g_part[i >> 8];
        g_rptr[i] = r;
        g_cur[i] = r;
    }
}
__global__ void k_permute(const void* __restrict__ ei_) {
    int e = blockIdx.x * 256 + threadIdx.x;
    int s, d;
    if (g_is64) {
        const long long* E = (const long long*)ei_;
        s = (int)E[e]; d = (int)E[NE + e];
    } else {
        const int* E = (const int*)ei_;
        s = E[e]; d = E[NE + e];
    }
    int pos = atomicAdd(&g_cur[d], 1);
    g_csrc[pos] = s;
}

// ------- h0 = x @ W0 + b0; zero pooled accumulators -------
__global__ void __launch_bounds__(256) k_lin0(const float* __restrict__ x,
                                              const float* __restrict__ W0,
                                              const float* __restrict__ b0) {
    __shared__ float sW[11 * 64];
    __shared__ float sB[64];
    int t = threadIdx.x;
    for (int i = t; i < 11 * 64; i += 256) sW[i] = W0[i];
    if (t < 64) sB[t] = b0[t];
    __syncthreads();

    int gid = blockIdx.x * 256 + t;
    int n = gid >> 6, j = gid & 63;
    const float* xr = x + n * 11;
    float acc = sB[j];
    #pragma unroll
    for (int k = 0; k < 11; k++) acc += xr[k] * sW[k * 64 + j];
    g_bufA[gid] = acc;
    if (gid < NG * 16) g_sums[gid] = 0.0f;
    if (gid < NG)      g_cnts[gid] = 0.0f;
}

// ---------------- pull gather: agg[d] = sum_{e: dst=d} h[src[e]] ----------------
// 16 threads per node (one float4 column each); CSR row loop, unroll 2.
__global__ void __launch_bounds__(256) k_gather(int in_sel) {
    const float4* __restrict__ h = (const float4*)(in_sel ? g_bufB : g_bufA);
    int grp = blockIdx.x * 16 + (threadIdx.x >> 4);   // 6250*16 = NN exact
    int c = threadIdx.x & 15;
    int r0 = g_rptr[grp], r1 = g_rptr[grp + 1];
    float4 acc = make_float4(0.f, 0.f, 0.f, 0.f);
    int i = r0;
    for (; i + 2 <= r1; i += 2) {
        int s0 = g_csrc[i], s1 = g_csrc[i + 1];
        float4 v0 = h[s0 * 16 + c];
        float4 v1 = h[s1 * 16 + c];
        acc.x += v0.x; acc.y += v0.y; acc.z += v0.z; acc.w += v0.w;
        acc.x += v1.x; acc.y += v1.y; acc.z += v1.z; acc.w += v1.w;
    }
    if (i < r1) {
        int s0 = g_csrc[i];
        float4 v0 = h[s0 * 16 + c];
        acc.x += v0.x; acc.y += v0.y; acc.z += v0.z; acc.w += v0.w;
    }
    ((float4*)g_agg)[grp * 16 + c] = acc;
}

// -------- conv: h_out = tanh(agg @ Wrel + brel + h_in @ Wroot) --------------------
__global__ void __launch_bounds__(256) k_conv(int in_sel,
                                              const float* __restrict__ Wrel,
                                              const float* __restrict__ brel,
                                              const float* __restrict__ Wroot,
                                              int out_sel) {
    extern __shared__ __align__(16) char sm_[];
    const float* __restrict__ hin  = in_sel  ? g_bufB : g_bufA;
    float* __restrict__       hout = out_sel ? g_bufB : g_bufA;
    int t = threadIdx.x;
    int n0 = blockIdx.x * 128;

#if defined(__CUDA_ARCH_FEAT_SM103_ALL)
    int wid = t >> 5, lid = t & 31;
    int valid = NN - n0; if (valid > 128) valid = 128;
    unsigned smb = smem_u32(sm_);

    if (wid == 0) {
        asm volatile("tcgen05.alloc.cta_group::1.sync.aligned.shared::cta.b32 [%0], %1;"
                     :: "r"(smb + SM_TMEM), "r"(128u) : "memory");
        asm volatile("tcgen05.relinquish_alloc_permit.cta_group::1.sync.aligned;");
    }
    if (t == 0)
        asm volatile("mbarrier.init.shared.b64 [%0], %1;" :: "r"(smb + SM_MBAR), "r"(1u) : "memory");
    if (t < 64) ((float*)(sm_ + SM_BIAS))[t] = brel[t];

    #pragma unroll
    for (int i = 0; i < 16; i++) {
        int idx = t + i * 256;
        int node = idx >> 5, q = idx & 31;
        if (node < valid) {
            float4 v = (q < 16) ? *(const float4*)&g_agg[(n0 + node) * 64 + q * 4]
                                : *(const float4*)&hin [(n0 + node) * 64 + (q - 16) * 4];
            uint4 u = make_uint4(f2tf32(v.x), f2tf32(v.y), f2tf32(v.z), f2tf32(v.w));
            *(uint4*)(sm_ + SM_A + a_off(node, q * 4)) = u;
        }
    }
    #pragma unroll
    for (int i = 0; i < 32; i++) {
        int idx = t + i * 256;
        int k = idx >> 6, j = idx & 63;
        float w = (k < 64) ? Wrel[k * 64 + j] : Wroot[(k - 64) * 64 + j];
        *(unsigned*)(sm_ + SM_B + b_off(j, k)) = f2tf32(w);
    }
    asm volatile("fence.proxy.async.shared::cta;" ::: "memory");
    __syncthreads();

    unsigned tmem;
    asm volatile("ld.shared.b32 %0, [%1];" : "=r"(tmem) : "r"(smb + SM_TMEM));

    if (wid == 0) {
        asm volatile("tcgen05.fence::after_thread_sync;" ::: "memory");
        unsigned ep;
        asm volatile("{ .reg .pred p; elect.sync _|p, 0xFFFFFFFF; selp.b32 %0, 1, 0, p; }" : "=r"(ep));
        if (ep) {
            ull da = DESC_BASE | (((ull)((smb + SM_A) >> 4)) & 0x3FFF);
            ull db = DESC_BASE | (((ull)((smb + SM_B) >> 4)) & 0x3FFF);
            #pragma unroll
            for (int s = 0; s < 16; s++) {
                int ac = s >> 2, kk = s & 3;
                unsigned en = (s > 0);
                asm volatile("{\n\t.reg .pred p;\n\tsetp.ne.u32 p, %4, 0;\n\t"
                             "tcgen05.mma.cta_group::1.kind::tf32 [%0], %1, %2, %3, p;\n\t}"
                             :: "r"(tmem), "l"(da + ac * 1024 + kk * 2),
                                "l"(db + ac * 512 + kk * 2), "r"(IDESC_TF32), "r"(en) : "memory");
            }
            asm volatile("tcgen05.commit.cta_group::1.mbarrier::arrive::one.shared::cluster.b64 [%0];"
                         :: "r"(smb + SM_MBAR) : "memory");
        }
    }

    {
        unsigned mb = smb + SM_MBAR, done;
        asm volatile("{\n\t.reg .pred p;\n\t"
                     "mbarrier.try_wait.parity.acquire.cta.shared::cta.b64 p, [%1], 0;\n\t"
                     "selp.b32 %0, 1, 0, p;\n\t}" : "=r"(done) : "r"(mb) : "memory");
        if (!done) {
            asm volatile("{\n\t.reg .pred P1;\n\t"
                         "W%=:\n\t"
                         "mbarrier.try_wait.parity.acquire.cta.shared::cta.b64 P1, [%0], 0, 0x989680;\n\t"
                         "@P1 bra.uni D%=;\n\t"
                         "bra.uni W%=;\n\t"
                         "D%=:\n\t}" :: "r"(mb) : "memory");
        }
    }
    asm volatile("tcgen05.fence::after_thread_sync;" ::: "memory");

    float* sOut = (float*)(sm_ + SM_A);
    const float* sBias = (float*)(sm_ + SM_BIAS);
    if (wid < 4) {
        unsigned r[64];
        asm volatile("tcgen05.ld.sync.aligned.32x32b.x32.b32 "
            "{%0,%1,%2,%3,%4,%5,%6,%7,%8,%9,%10,%11,%12,%13,%14,%15,"
            "%16,%17,%18,%19,%20,%21,%22,%23,%24,%25,%26,%27,%28,%29,%30,%31}, [%32];"
            : "=r"(r[0]),"=r"(r[1]),"=r"(r[2]),"=r"(r[3]),"=r"(r[4]),"=r"(r[5]),"=r"(r[6]),"=r"(r[7]),
              "=r"(r[8]),"=r"(r[9]),"=r"(r[10]),"=r"(r[11]),"=r"(r[12]),"=r"(r[13]),"=r"(r[14]),"=r"(r[15]),
              "=r"(r[16]),"=r"(r[17]),"=r"(r[18]),"=r"(r[19]),"=r"(r[20]),"=r"(r[21]),"=r"(r[22]),"=r"(r[23]),
              "=r"(r[24]),"=r"(r[25]),"=r"(r[26]),"=r"(r[27]),"=r"(r[28]),"=r"(r[29]),"=r"(r[30]),"=r"(r[31])
            : "r"(tmem));
        asm volatile("tcgen05.ld.sync.aligned.32x32b.x32.b32 "
            "{%0,%1,%2,%3,%4,%5,%6,%7,%8,%9,%10,%11,%12,%13,%14,%15,"
            "%16,%17,%18,%19,%20,%21,%22,%23,%24,%25,%26,%27,%28,%29,%30,%31}, [%32];"
            : "=r"(r[32]),"=r"(r[33]),"=r"(r[34]),"=r"(r[35]),"=r"(r[36]),"=r"(r[37]),"=r"(r[38]),"=r"(r[39]),
              "=r"(r[40]),"=r"(r[41]),"=r"(r[42]),"=r"(r[43]),"=r"(r[44]),"=r"(r[45]),"=r"(r[46]),"=r"(r[47]),
              "=r"(r[48]),"=r"(r[49]),"=r"(r[50]),"=r"(r[51]),"=r"(r[52]),"=r"(r[53]),"=r"(r[54]),"=r"(r[55]),
              "=r"(r[56]),"=r"(r[57]),"=r"(r[58]),"=r"(r[59]),"=r"(r[60]),"=r"(r[61]),"=r"(r[62]),"=r"(r[63])
            : "r"(tmem + 32));
        asm volatile("tcgen05.wait::ld.sync.aligned;" ::: "memory");

        int node = wid * 32 + lid;
        if (node < valid) {
            #pragma unroll
            for (int c = 0; c < 64; c += 2) {
                float2 o;
                o.x = tanhf(__uint_as_float(r[c])     + sBias[c]);
                o.y = tanhf(__uint_as_float(r[c + 1]) + sBias[c + 1]);
                *(float2*)&sOut[node * 66 + c] = o;
            }
        }
    }
    __syncthreads();

    if (t < 32) {
        if (t == 0)
            asm volatile("mbarrier.inval.shared.b64 [%0];" :: "r"(smb + SM_MBAR) : "memory");
        asm volatile("tcgen05.dealloc.cta_group::1.sync.aligned.b32 %0, %1;" :: "r"(tmem), "r"(128u));
    }

    #pragma unroll
    for (int i = 0; i < 8; i++) {
        int off = (t + i * 256) * 4;
        if (off < valid * 64) {
            int n = off >> 6, k = off & 63;
            const float* ps = &sOut[n * 66 + k];
            *(float4*)&hout[n0 * 64 + off] = make_float4(ps[0], ps[1], ps[2], ps[3]);
        }
    }
#else
    // ---------- scalar f32x2 fallback (non-103a PTX pass) ----------
    float* sA   = (float*)sm_;
    float* sH   = sA   + 64 * 66;
    float* sWrT = sH   + 64 * 66;
    float* sWoT = sWrT + 64 * 66;
    float* sB   = sWoT + 64 * 66;

    #pragma unroll
    for (int i = 0; i < 4; i++) {
        int idx4 = t + i * 256;
        float4 wr = ((const float4*)Wrel)[idx4];
        float4 wo = ((const float4*)Wroot)[idx4];
        int k = idx4 >> 4;
        int j = (idx4 & 15) * 4;
        sWrT[(j + 0) * 66 + k] = wr.x; sWrT[(j + 1) * 66 + k] = wr.y;
        sWrT[(j + 2) * 66 + k] = wr.z; sWrT[(j + 3) * 66 + k] = wr.w;
        sWoT[(j + 0) * 66 + k] = wo.x; sWoT[(j + 1) * 66 + k] = wo.y;
        sWoT[(j + 2) * 66 + k] = wo.z; sWoT[(j + 3) * 66 + k] = wo.w;
    }
    if (t < 64) sB[t] = brel[t];

    for (int half = 0; half < 2; half++) {
        int m0 = n0 + half * 64;
        if (m0 >= NN) break;
        int vlim = (NN - m0) * 64; if (vlim > 4096) vlim = 4096;
        __syncthreads();
        #pragma unroll
        for (int i = 0; i < 4; i++) {
            int off = (t + i * 256) * 4;
            int n = off >> 6, k = off & 63;
            float4 va, vh;
            if (off < vlim) {
                va = *(const float4*)&g_agg[m0 * 64 + off];
                vh = *(const float4*)&hin [m0 * 64 + off];
            } else { va = make_float4(0.f,0.f,0.f,0.f); vh = va; }
            float* pa = &sA[n * 66 + k];
            float* ph = &sH[n * 66 + k];
            pa[0] = va.x; pa[1] = va.y; pa[2] = va.z; pa[3] = va.w;
            ph[0] = vh.x; ph[1] = vh.y; ph[2] = vh.z; ph[3] = vh.w;
        }
        __syncthreads();

        int jq = t & 15;
        int nb = (t >> 4) * 4;
        ull acc[4][4];
        #pragma unroll
        for (int n = 0; n < 4; n++)
            #pragma unroll
            for (int c = 0; c < 4; c++) acc[n][c] = 0ull;

        const float* pa = &sA[nb * 66];
        const float* ph = &sH[nb * 66];
        const float* pwr = &sWrT[jq * 66];
        const float* pwo = &sWoT[jq * 66];

        #pragma unroll 2
        for (int k = 0; k < 64; k += 2) {
            ull wr[4], wo[4], a[4], h[4];
            #pragma unroll
            for (int c = 0; c < 4; c++) {
                wr[c] = *(const ull*)(pwr + c * 16 * 66 + k);
                wo[c] = *(const ull*)(pwo + c * 16 * 66 + k);
            }
            #pragma unroll
            for (int n = 0; n < 4; n++) {
                a[n] = *(const ull*)(pa + n * 66 + k);
                h[n] = *(const ull*)(ph + n * 66 + k);
            }
            #pragma unroll
            for (int n = 0; n < 4; n++) {
                #pragma unroll
                for (int c = 0; c < 4; c++) {
                    acc[n][c] = fma2(a[n], wr[c], acc[n][c]);
                    acc[n][c] = fma2(h[n], wo[c], acc[n][c]);
                }
            }
        }

        __syncthreads();
        #pragma unroll
        for (int n = 0; n < 4; n++) {
            #pragma unroll
            for (int c = 0; c < 4; c++) {
                int col = jq + 16 * c;
                float2 p = *(float2*)&acc[n][c];
                sA[(nb + n) * 66 + col] = tanhf(p.x + p.y + sB[col]);
            }
        }
        __syncthreads();
        #pragma unroll
        for (int i = 0; i < 4; i++) {
            int off = (t + i * 256) * 4;
            if (off < vlim) {
                int n = off >> 6, k = off & 63;
                const float* ps = &sA[n * 66 + k];
                *(float4*)&hout[m0 * 64 + off] = make_float4(ps[0], ps[1], ps[2], ps[3]);
            }
        }
    }
#endif
}

// -------- h3 = tanh(h2 @ W3 + b3) + pooled sums via smem-staged rows --------
__global__ void __launch_bounds__(256) k_lin3pool(const void* __restrict__ bat_,
                                                  const float* __restrict__ W3,
                                                  const float* __restrict__ b3) {
    __shared__ float sW[64 * 16];
    __shared__ float sB[16];
    __shared__ float sRow[16 * 65];
    int t = threadIdx.x;
    for (int i = t; i < 64 * 16; i += 256) sW[i] = W3[i];
    if (t < 16) sB[t] = b3[t];

    int n0 = blockIdx.x * 16;                 // 6250 blocks, exact
    {
        int off = t * 4;                      // 16 rows x 64 floats = 256 float4
        int n = off >> 6, k = off & 63;
        float4 v = *(const float4*)&g_bufA[(n0 + n) * 64 + k];
        float* p = &sRow[n * 65 + k];
        p[0] = v.x; p[1] = v.y; p[2] = v.z; p[3] = v.w;
    }
    __syncthreads();

    int n = t >> 4, j = t & 15;
    const float* hr = &sRow[n * 65];
    float acc = sB[j];
    #pragma unroll
    for (int k = 0; k < 64; k++) acc += hr[k] * sW[k * 16 + j];
    float v = tanhf(acc);
    int node = n0 + n;
    int g;
    if (g_is64) g = (int)((const long long*)bat_)[node];
    else        g = ((const int*)bat_)[node];
    atomicAdd(&g_sums[g * 16 + j], v);
    if (j == 0) atomicAdd(&g_cnts[g], 1.0f);
}

// ---------------- mean pool + NormalParamExtractor ------------------------------
__global__ void k_final(float* __restrict__ out) {
    int t = blockIdx.x * blockDim.x + threadIdx.x;
    if (t >= NG * 16) return;
    int g = t >> 4, j = t & 15;
    float m = g_sums[t] / fmaxf(g_cnts[g], 1.0f);
    if (j < 8) {
        out[g * 8 + j] = m;
    } else {
        float s = m + 0.54132485461292192f;
        float sp = (s > 20.0f) ? s : log1pf(expf(s));
        out[NG * 8 + g * 8 + (j - 8)] = fmaxf(sp, 1e-4f);
    }
}

// ---------------- launch ---------------------------------------------------------
extern "C" void kernel_launch(void* const* d_in, const int* in_sizes, int n_in,
                              void* d_out, int out_size) {
    const float* x     = (const float*)d_in[0];
    const void*  ei    = d_in[1];
    const void*  bat   = d_in[2];
    const float* W0    = (const float*)d_in[3];
    const float* b0    = (const float*)d_in[4];
    const float* Wrel1 = (const float*)d_in[5];
    const float* brel1 = (const float*)d_in[6];
    const float* Wroot1= (const float*)d_in[7];
    const float* Wrel2 = (const float*)d_in[8];
    const float* brel2 = (const float*)d_in[9];
    const float* Wroot2= (const float*)d_in[10];
    const float* W3    = (const float*)d_in[11];
    const float* b3    = (const float*)d_in[12];
    float* out = (float*)d_out;

    cudaFuncSetAttribute(k_conv, cudaFuncAttributeMaxDynamicSharedMemorySize, SM_TOTAL);

    // --- CSR build (indices only; reused by both layers) ---
    k_detect<<<1, 32>>>((const unsigned int*)ei);
    k_zdeg<<<NB_SCAN, 256>>>();
    k_hist<<<NE / 256, 256>>>(ei);
    k_scan1<<<NB_SCAN, 256>>>();
    k_scan2<<<1, 512>>>();
    k_scan3<<<NB_SCAN, 256>>>();
    k_permute<<<NE / 256, 256>>>(ei);

    k_lin0<<<NN * 64 / 256, 256>>>(x, W0, b0);          // h0 -> bufA; sums/cnts = 0

    const int CONV_GRID = (NN + 127) / 128;             // 782
    k_gather<<<NN / 16, 256>>>(0);                      // agg = sum h0[src]
    k_conv<<<CONV_GRID, 256, SM_TOTAL>>>(0, Wrel1, brel1, Wroot1, 1);  // h1 -> bufB

    k_gather<<<NN / 16, 256>>>(1);                      // agg = sum h1[src]
    k_conv<<<CONV_GRID, 256, SM_TOTAL>>>(1, Wrel2, brel2, Wroot2, 0);  // h2 -> bufA

    k_lin3pool<<<NN / 16, 256>>>(bat, W3, b3);
    k_final<<<(NG * 16 + 255) / 256, 256>>>(out);
}

// round 16
// speedup vs baseline: 1.1001x; 1.0021x over previous
#include <cuda_runtime.h>
#include <math.h>

#define NN 100000
#define NE 1600000
#define NG 512
#define NB_SCAN 391            // ceil(NN/256)

typedef unsigned long long ull;

// ---------------- device scratch ----------------
__device__ int   g_is64;
__device__ float g_bufA[NN * 64];
__device__ float g_bufB[NN * 64];
__device__ float g_agg [NN * 64];
__device__ float g_sums[NG * 16];
__device__ float g_cnts[NG];
// CSR scratch
__device__ int g_deg [NN];
__device__ int g_excl[NN];
__device__ int g_part[512];
__device__ int g_rptr[NN + 1];
__device__ int g_cur [NN];
__device__ int g_csrc[NE];

// ---------------- dynamic smem layout for k_conv (MMA path) ----------------
#define SM_TMEM 0
#define SM_MBAR 8
#define SM_BIAS 16
#define SM_A    1024                 // 128x128 tf32, blocked SW128 atoms: 65536 B
#define SM_B    (1024 + 65536)       // 64x128 tf32: 32768 B
#define SM_TOTAL (SM_B + 32768)      // 99328 B

// idesc: d=F32(1<<4), a=TF32(2<<7), b=TF32(2<<10), N=64 (8<<17), M=128 (8<<24)
#define IDESC_TF32 ((1u<<4)|(2u<<7)|(2u<<10)|(8u<<17)|(8u<<24))

static __device__ __forceinline__ ull fma2(ull a, ull b, ull c) {
    ull d;
    asm("fma.rn.f32x2 %0, %1, %2, %3;" : "=l"(d) : "l"(a), "l"(b), "l"(c));
    return d;
}
static __device__ __forceinline__ unsigned smem_u32(const void* p) {
    unsigned a;
    asm("{ .reg .u64 t; cvta.to.shared.u64 t, %1; cvt.u32.u64 %0, t; }" : "=r"(a) : "l"(p));
    return a;
}
static __device__ __forceinline__ unsigned f2tf32(float f) {
    unsigned r;
    asm("cvt.rna.satfinite.tf32.f32 %0, %1;" : "=r"(r) : "f"(f));
    return r;
}
static __device__ __forceinline__ int a_off(int node, int kcol) {
    int b = (((node >> 3) + (kcol >> 5) * 16) << 10) + ((node & 7) << 7) + ((kcol & 31) << 2);
    return b ^ ((b >> 3) & 0x70);
}
static __device__ __forceinline__ int b_off(int j, int k) {
    int b = (((j >> 3) + (k >> 5) * 8) << 10) + ((j & 7) << 7) + ((k & 31) << 2);
    return b ^ ((b >> 3) & 0x70);
}
#define DESC_BASE ((2ULL<<61)|(1ULL<<46)|(64ULL<<32)|(1ULL<<16))

// ---------------- dtype detection ----------------
__global__ void k_detect(const unsigned int* __restrict__ ei) {
    if (threadIdx.x == 0) {
        int is64 = 1;
        #pragma unroll 1
        for (int i = 1; i < 128; i += 2) {
            if (ei[i] != 0u) { is64 = 0; break; }
        }
        g_is64 = is64;
    }
}

// ---------------- CSR build ----------------
__global__ void k_zdeg() {
    int i = blockIdx.x * 256 + threadIdx.x;
    if (i < NN) g_deg[i] = 0;
}
__global__ void k_hist(const void* __restrict__ ei_) {
    int e = blockIdx.x * 256 + threadIdx.x;
    int d;
    if (g_is64) d = (int)((const long long*)ei_)[NE + e];
    else        d = ((const int*)ei_)[NE + e];
    atomicAdd(&g_deg[d], 1);
}
__global__ void k_scan1() {
    __shared__ int s[256];
    int t = threadIdx.x;
    int i = blockIdx.x * 256 + t;
    int v = (i < NN) ? g_deg[i] : 0;
    s[t] = v;
    __syncthreads();
    #pragma unroll
    for (int ofs = 1; ofs < 256; ofs <<= 1) {
        int add = (t >= ofs) ? s[t - ofs] : 0;
        __syncthreads();
        s[t] += add;
        __syncthreads();
    }
    if (i < NN) g_excl[i] = s[t] - v;
    if (t == 255) g_part[blockIdx.x] = s[t];
}
__global__ void k_scan2() {
    __shared__ int s[512];
    int t = threadIdx.x;
    int v = (t < NB_SCAN) ? g_part[t] : 0;
    s[t] = v;
    __syncthreads();
    #pragma unroll
    for (int ofs = 1; ofs < 512; ofs <<= 1) {
        int add = (t >= ofs) ? s[t - ofs] : 0;
        __syncthreads();
        s[t] += add;
        __syncthreads();
    }
    if (t < NB_SCAN) g_part[t] = s[t] - v;
    if (t == 0) g_rptr[NN] = NE;
}
__global__ void k_scan3() {
    int i = blockIdx.x * 256 + threadIdx.x;
    if (i < NN) {
        int r = g_excl[i] + g_part[i >> 8];
        g_rptr[i] = r;
        g_cur[i] = r;
    }
}
__global__ void k_permute(const void* __restrict__ ei_) {
    int e = blockIdx.x * 256 + threadIdx.x;
    int s, d;
    if (g_is64) {
        const long long* E = (const long long*)ei_;
        s = (int)E[e]; d = (int)E[NE + e];
    } else {
        const int* E = (const int*)ei_;
        s = E[e]; d = E[NE + e];
    }
    int pos = atomicAdd(&g_cur[d], 1);
    g_csrc[pos] = s;
}

// ------- h0 = x @ W0 + b0; zero pooled accumulators -------
__global__ void __launch_bounds__(256) k_lin0(const float* __restrict__ x,
                                              const float* __restrict__ W0,
                                              const float* __restrict__ b0) {
    __shared__ float sW[11 * 64];
    __shared__ float sB[64];
    int t = threadIdx.x;
    for (int i = t; i < 11 * 64; i += 256) sW[i] = W0[i];
    if (t < 64) sB[t] = b0[t];
    __syncthreads();

    int gid = blockIdx.x * 256 + t;
    int n = gid >> 6, j = gid & 63;
    const float* xr = x + n * 11;
    float acc = sB[j];
    #pragma unroll
    for (int k = 0; k < 11; k++) acc += xr[k] * sW[k * 64 + j];
    g_bufA[gid] = acc;
    if (gid < NG * 16) g_sums[gid] = 0.0f;
    if (gid < NG)      g_cnts[gid] = 0.0f;
}

// ---------------- pull gather: agg[d] = sum_{e: dst=d} h[src[e]] ----------------
// 16 threads per node (one float4 column each); CSR row loop, unroll 2.
__global__ void __launch_bounds__(256) k_gather(int in_sel) {
    const float4* __restrict__ h = (const float4*)(in_sel ? g_bufB : g_bufA);
    int grp = blockIdx.x * 16 + (threadIdx.x >> 4);   // 6250*16 = NN exact
    int c = threadIdx.x & 15;
    int r0 = g_rptr[grp], r1 = g_rptr[grp + 1];
    float4 acc = make_float4(0.f, 0.f, 0.f, 0.f);
    int i = r0;
    for (; i + 2 <= r1; i += 2) {
        int s0 = g_csrc[i], s1 = g_csrc[i + 1];
        float4 v0 = h[s0 * 16 + c];
        float4 v1 = h[s1 * 16 + c];
        acc.x += v0.x; acc.y += v0.y; acc.z += v0.z; acc.w += v0.w;
        acc.x += v1.x; acc.y += v1.y; acc.z += v1.z; acc.w += v1.w;
    }
    if (i < r1) {
        int s0 = g_csrc[i];
        float4 v0 = h[s0 * 16 + c];
        acc.x += v0.x; acc.y += v0.y; acc.z += v0.z; acc.w += v0.w;
    }
    ((float4*)g_agg)[grp * 16 + c] = acc;
}

// -------- conv: h_out = tanh(agg @ Wrel + brel + h_in @ Wroot) --------------------
__global__ void __launch_bounds__(256) k_conv(int in_sel,
                                              const float* __restrict__ Wrel,
                                              const float* __restrict__ brel,
                                              const float* __restrict__ Wroot,
                                              int out_sel) {
    extern __shared__ __align__(16) char sm_[];
    const float* __restrict__ hin  = in_sel  ? g_bufB : g_bufA;
    float* __restrict__       hout = out_sel ? g_bufB : g_bufA;
    int t = threadIdx.x;
    int n0 = blockIdx.x * 128;

#if defined(__CUDA_ARCH_FEAT_SM103_ALL)
    int wid = t >> 5, lid = t & 31;
    int valid = NN - n0; if (valid > 128) valid = 128;
    unsigned smb = smem_u32(sm_);

    if (wid == 0) {
        asm volatile("tcgen05.alloc.cta_group::1.sync.aligned.shared::cta.b32 [%0], %1;"
                     :: "r"(smb + SM_TMEM), "r"(128u) : "memory");
        asm volatile("tcgen05.relinquish_alloc_permit.cta_group::1.sync.aligned;");
    }
    if (t == 0)
        asm volatile("mbarrier.init.shared.b64 [%0], %1;" :: "r"(smb + SM_MBAR), "r"(1u) : "memory");
    if (t < 64) ((float*)(sm_ + SM_BIAS))[t] = brel[t];

    #pragma unroll
    for (int i = 0; i < 16; i++) {
        int idx = t + i * 256;
        int node = idx >> 5, q = idx & 31;
        if (node < valid) {
            float4 v = (q < 16) ? *(const float4*)&g_agg[(n0 + node) * 64 + q * 4]
                                : *(const float4*)&hin [(n0 + node) * 64 + (q - 16) * 4];
            uint4 u = make_uint4(f2tf32(v.x), f2tf32(v.y), f2tf32(v.z), f2tf32(v.w));
            *(uint4*)(sm_ + SM_A + a_off(node, q * 4)) = u;
        }
    }
    #pragma unroll
    for (int i = 0; i < 32; i++) {
        int idx = t + i * 256;
        int k = idx >> 6, j = idx & 63;
        float w = (k < 64) ? Wrel[k * 64 + j] : Wroot[(k - 64) * 64 + j];
        *(unsigned*)(sm_ + SM_B + b_off(j, k)) = f2tf32(w);
    }
    asm volatile("fence.proxy.async.shared::cta;" ::: "memory");
    __syncthreads();

    unsigned tmem;
    asm volatile("ld.shared.b32 %0, [%1];" : "=r"(tmem) : "r"(smb + SM_TMEM));

    if (wid == 0) {
        asm volatile("tcgen05.fence::after_thread_sync;" ::: "memory");
        unsigned ep;
        asm volatile("{ .reg .pred p; elect.sync _|p, 0xFFFFFFFF; selp.b32 %0, 1, 0, p; }" : "=r"(ep));
        if (ep) {
            ull da = DESC_BASE | (((ull)((smb + SM_A) >> 4)) & 0x3FFF);
            ull db = DESC_BASE | (((ull)((smb + SM_B) >> 4)) & 0x3FFF);
            #pragma unroll
            for (int s = 0; s < 16; s++) {
                int ac = s >> 2, kk = s & 3;
                unsigned en = (s > 0);
                asm volatile("{\n\t.reg .pred p;\n\tsetp.ne.u32 p, %4, 0;\n\t"
                             "tcgen05.mma.cta_group::1.kind::tf32 [%0], %1, %2, %3, p;\n\t}"
                             :: "r"(tmem), "l"(da + ac * 1024 + kk * 2),
                                "l"(db + ac * 512 + kk * 2), "r"(IDESC_TF32), "r"(en) : "memory");
            }
            asm volatile("tcgen05.commit.cta_group::1.mbarrier::arrive::one.shared::cluster.b64 [%0];"
                         :: "r"(smb + SM_MBAR) : "memory");
        }
    }

    {
        unsigned mb = smb + SM_MBAR, done;
        asm volatile("{\n\t.reg .pred p;\n\t"
                     "mbarrier.try_wait.parity.acquire.cta.shared::cta.b64 p, [%1], 0;\n\t"
                     "selp.b32 %0, 1, 0, p;\n\t}" : "=r"(done) : "r"(mb) : "memory");
        if (!done) {
            asm volatile("{\n\t.reg .pred P1;\n\t"
                         "W%=:\n\t"
                         "mbarrier.try_wait.parity.acquire.cta.shared::cta.b64 P1, [%0], 0, 0x989680;\n\t"
                         "@P1 bra.uni D%=;\n\t"
                         "bra.uni W%=;\n\t"
                         "D%=:\n\t}" :: "r"(mb) : "memory");
        }
    }
    asm volatile("tcgen05.fence::after_thread_sync;" ::: "memory");

    float* sOut = (float*)(sm_ + SM_A);
    const float* sBias = (float*)(sm_ + SM_BIAS);
    if (wid < 4) {
        unsigned r[64];
        asm volatile("tcgen05.ld.sync.aligned.32x32b.x32.b32 "
            "{%0,%1,%2,%3,%4,%5,%6,%7,%8,%9,%10,%11,%12,%13,%14,%15,"
            "%16,%17,%18,%19,%20,%21,%22,%23,%24,%25,%26,%27,%28,%29,%30,%31}, [%32];"
            : "=r"(r[0]),"=r"(r[1]),"=r"(r[2]),"=r"(r[3]),"=r"(r[4]),"=r"(r[5]),"=r"(r[6]),"=r"(r[7]),
              "=r"(r[8]),"=r"(r[9]),"=r"(r[10]),"=r"(r[11]),"=r"(r[12]),"=r"(r[13]),"=r"(r[14]),"=r"(r[15]),
              "=r"(r[16]),"=r"(r[17]),"=r"(r[18]),"=r"(r[19]),"=r"(r[20]),"=r"(r[21]),"=r"(r[22]),"=r"(r[23]),
              "=r"(r[24]),"=r"(r[25]),"=r"(r[26]),"=r"(r[27]),"=r"(r[28]),"=r"(r[29]),"=r"(r[30]),"=r"(r[31])
            : "r"(tmem));
        asm volatile("tcgen05.ld.sync.aligned.32x32b.x32.b32 "
            "{%0,%1,%2,%3,%4,%5,%6,%7,%8,%9,%10,%11,%12,%13,%14,%15,"
            "%16,%17,%18,%19,%20,%21,%22,%23,%24,%25,%26,%27,%28,%29,%30,%31}, [%32];"
            : "=r"(r[32]),"=r"(r[33]),"=r"(r[34]),"=r"(r[35]),"=r"(r[36]),"=r"(r[37]),"=r"(r[38]),"=r"(r[39]),
              "=r"(r[40]),"=r"(r[41]),"=r"(r[42]),"=r"(r[43]),"=r"(r[44]),"=r"(r[45]),"=r"(r[46]),"=r"(r[47]),
              "=r"(r[48]),"=r"(r[49]),"=r"(r[50]),"=r"(r[51]),"=r"(r[52]),"=r"(r[53]),"=r"(r[54]),"=r"(r[55]),
              "=r"(r[56]),"=r"(r[57]),"=r"(r[58]),"=r"(r[59]),"=r"(r[60]),"=r"(r[61]),"=r"(r[62]),"=r"(r[63])
            : "r"(tmem + 32));
        asm volatile("tcgen05.wait::ld.sync.aligned;" ::: "memory");

        int node = wid * 32 + lid;
        if (node < valid) {
            #pragma unroll
            for (int c = 0; c < 64; c += 2) {
                float2 o;
                o.x = tanhf(__uint_as_float(r[c])     + sBias[c]);
                o.y = tanhf(__uint_as_float(r[c + 1]) + sBias[c + 1]);
                *(float2*)&sOut[node * 66 + c] = o;
            }
        }
    }
    __syncthreads();

    if (t < 32) {
        if (t == 0)
            asm volatile("mbarrier.inval.shared.b64 [%0];" :: "r"(smb + SM_MBAR) : "memory");
        asm volatile("tcgen05.dealloc.cta_group::1.sync.aligned.b32 %0, %1;" :: "r"(tmem), "r"(128u));
    }

    #pragma unroll
    for (int i = 0; i < 8; i++) {
        int off = (t + i * 256) * 4;
        if (off < valid * 64) {
            int n = off >> 6, k = off & 63;
            const float* ps = &sOut[n * 66 + k];
            *(float4*)&hout[n0 * 64 + off] = make_float4(ps[0], ps[1], ps[2], ps[3]);
        }
    }
#else
    // ---------- scalar f32x2 fallback (non-103a PTX pass) ----------
    float* sA   = (float*)sm_;
    float* sH   = sA   + 64 * 66;
    float* sWrT = sH   + 64 * 66;
    float* sWoT = sWrT + 64 * 66;
    float* sB   = sWoT + 64 * 66;

    #pragma unroll
    for (int i = 0; i < 4; i++) {
        int idx4 = t + i * 256;
        float4 wr = ((const float4*)Wrel)[idx4];
        float4 wo = ((const float4*)Wroot)[idx4];
        int k = idx4 >> 4;
        int j = (idx4 & 15) * 4;
        sWrT[(j + 0) * 66 + k] = wr.x; sWrT[(j + 1) * 66 + k] = wr.y;
        sWrT[(j + 2) * 66 + k] = wr.z; sWrT[(j + 3) * 66 + k] = wr.w;
        sWoT[(j + 0) * 66 + k] = wo.x; sWoT[(j + 1) * 66 + k] = wo.y;
        sWoT[(j + 2) * 66 + k] = wo.z; sWoT[(j + 3) * 66 + k] = wo.w;
    }
    if (t < 64) sB[t] = brel[t];

    for (int half = 0; half < 2; half++) {
        int m0 = n0 + half * 64;
        if (m0 >= NN) break;
        int vlim = (NN - m0) * 64; if (vlim > 4096) vlim = 4096;
        __syncthreads();
        #pragma unroll
        for (int i = 0; i < 4; i++) {
            int off = (t + i * 256) * 4;
            int n = off >> 6, k = off & 63;
            float4 va, vh;
            if (off < vlim) {
                va = *(const float4*)&g_agg[m0 * 64 + off];
                vh = *(const float4*)&hin [m0 * 64 + off];
            } else { va = make_float4(0.f,0.f,0.f,0.f); vh = va; }
            float* pa = &sA[n * 66 + k];
            float* ph = &sH[n * 66 + k];
            pa[0] = va.x; pa[1] = va.y; pa[2] = va.z; pa[3] = va.w;
            ph[0] = vh.x; ph[1] = vh.y; ph[2] = vh.z; ph[3] = vh.w;
        }
        __syncthreads();

        int jq = t & 15;
        int nb = (t >> 4) * 4;
        ull acc[4][4];
        #pragma unroll
        for (int n = 0; n < 4; n++)
            #pragma unroll
            for (int c = 0; c < 4; c++) acc[n][c] = 0ull;

        const float* pa = &sA[nb * 66];
        const float* ph = &sH[nb * 66];
        const float* pwr = &sWrT[jq * 66];
        const float* pwo = &sWoT[jq * 66];

        #pragma unroll 2
        for (int k = 0; k < 64; k += 2) {
            ull wr[4], wo[4], a[4], h[4];
            #pragma unroll
            for (int c = 0; c < 4; c++) {
                wr[c] = *(const ull*)(pwr + c * 16 * 66 + k);
                wo[c] = *(const ull*)(pwo + c * 16 * 66 + k);
            }
            #pragma unroll
            for (int n = 0; n < 4; n++) {
                a[n] = *(const ull*)(pa + n * 66 + k);
                h[n] = *(const ull*)(ph + n * 66 + k);
            }
            #pragma unroll
            for (int n = 0; n < 4; n++) {
                #pragma unroll
                for (int c = 0; c < 4; c++) {
                    acc[n][c] = fma2(a[n], wr[c], acc[n][c]);
                    acc[n][c] = fma2(h[n], wo[c], acc[n][c]);
                }
            }
        }

        __syncthreads();
        #pragma unroll
        for (int n = 0; n < 4; n++) {
            #pragma unroll
            for (int c = 0; c < 4; c++) {
                int col = jq + 16 * c;
                float2 p = *(float2*)&acc[n][c];
                sA[(nb + n) * 66 + col] = tanhf(p.x + p.y + sB[col]);
            }
        }
        __syncthreads();
        #pragma unroll
        for (int i = 0; i < 4; i++) {
            int off = (t + i * 256) * 4;
            if (off < vlim) {
                int n = off >> 6, k = off & 63;
                const float* ps = &sA[n * 66 + k];
                *(float4*)&hout[m0 * 64 + off] = make_float4(ps[0], ps[1], ps[2], ps[3]);
            }
        }
    }
#endif
}

// -------- h3 = tanh(h2 @ W3 + b3) + pooled sums via smem-staged rows --------
__global__ void __launch_bounds__(256) k_lin3pool(const void* __restrict__ bat_,
                                                  const float* __restrict__ W3,
                                                  const float* __restrict__ b3) {
    __shared__ float sW[64 * 16];
    __shared__ float sB[16];
    __shared__ float sRow[16 * 65];
    int t = threadIdx.x;
    for (int i = t; i < 64 * 16; i += 256) sW[i] = W3[i];
    if (t < 16) sB[t] = b3[t];

    int n0 = blockIdx.x * 16;                 // 6250 blocks, exact
    {
        int off = t * 4;                      // 16 rows x 64 floats = 256 float4
        int n = off >> 6, k = off & 63;
        float4 v = *(const float4*)&g_bufA[(n0 + n) * 64 + k];
        float* p = &sRow[n * 65 + k];
        p[0] = v.x; p[1] = v.y; p[2] = v.z; p[3] = v.w;
    }
    __syncthreads();

    int n = t >> 4, j = t & 15;
    const float* hr = &sRow[n * 65];
    float acc = sB[j];
    #pragma unroll
    for (int k = 0; k < 64; k++) acc += hr[k] * sW[k * 16 + j];
    float v = tanhf(acc);
    int node = n0 + n;
    int g;
    if (g_is64) g = (int)((const long long*)bat_)[node];
    else        g = ((const int*)bat_)[node];
    atomicAdd(&g_sums[g * 16 + j], v);
    if (j == 0) atomicAdd(&g_cnts[g], 1.0f);
}

// ---------------- mean pool + NormalParamExtractor ------------------------------
__global__ void k_final(float* __restrict__ out) {
    int t = blockIdx.x * blockDim.x + threadIdx.x;
    if (t >= NG * 16) return;
    int g = t >> 4, j = t & 15;
    float m = g_sums[t] / fmaxf(g_cnts[g], 1.0f);
    if (j < 8) {
        out[g * 8 + j] = m;
    } else {
        float s = m + 0.54132485461292192f;
        float sp = (s > 20.0f) ? s : log1pf(expf(s));
        out[NG * 8 + g * 8 + (j - 8)] = fmaxf(sp, 1e-4f);
    }
}

// ---------------- launch: fork-join graph (CSR build || lin0) --------------------
extern "C" void kernel_launch(void* const* d_in, const int* in_sizes, int n_in,
                              void* d_out, int out_size) {
    const float* x     = (const float*)d_in[0];
    const void*  ei    = d_in[1];
    const void*  bat   = d_in[2];
    const float* W0    = (const float*)d_in[3];
    const float* b0    = (const float*)d_in[4];
    const float* Wrel1 = (const float*)d_in[5];
    const float* brel1 = (const float*)d_in[6];
    const float* Wroot1= (const float*)d_in[7];
    const float* Wrel2 = (const float*)d_in[8];
    const float* brel2 = (const float*)d_in[9];
    const float* Wroot2= (const float*)d_in[10];
    const float* W3    = (const float*)d_in[11];
    const float* b3    = (const float*)d_in[12];
    float* out = (float*)d_out;

    cudaFuncSetAttribute(k_conv, cudaFuncAttributeMaxDynamicSharedMemorySize, SM_TOTAL);

    // Side stream + events for the fork-join (host-side resources; no device mem).
    cudaStream_t s2;
    cudaStreamCreateWithFlags(&s2, cudaStreamNonBlocking);
    cudaEvent_t evFork, evJoin;
    cudaEventCreateWithFlags(&evFork, cudaEventDisableTiming);
    cudaEventCreateWithFlags(&evJoin, cudaEventDisableTiming);

    // --- fork: CSR build on s2, lin0 on the main (capture) stream ---
    cudaEventRecord(evFork, 0);
    cudaStreamWaitEvent(s2, evFork, 0);

    k_detect<<<1, 32, 0, s2>>>((const unsigned int*)ei);
    k_zdeg<<<NB_SCAN, 256, 0, s2>>>();
    k_hist<<<NE / 256, 256, 0, s2>>>(ei);
    k_scan1<<<NB_SCAN, 256, 0, s2>>>();
    k_scan2<<<1, 512, 0, s2>>>();
    k_scan3<<<NB_SCAN, 256, 0, s2>>>();
    k_permute<<<NE / 256, 256, 0, s2>>>(ei);
    cudaEventRecord(evJoin, s2);

    k_lin0<<<NN * 64 / 256, 256>>>(x, W0, b0);          // h0 -> bufA; sums/cnts = 0

    // --- join: gathers need both lin0 (h0) and the CSR ---
    cudaStreamWaitEvent(0, evJoin, 0);

    const int CONV_GRID = (NN + 127) / 128;             // 782
    k_gather<<<NN / 16, 256>>>(0);                      // agg = sum h0[src]
    k_conv<<<CONV_GRID, 256, SM_TOTAL>>>(0, Wrel1, brel1, Wroot1, 1);  // h1 -> bufB

    k_gather<<<NN / 16, 256>>>(1);                      // agg = sum h1[src]
    k_conv<<<CONV_GRID, 256, SM_TOTAL>>>(1, Wrel2, brel2, Wroot2, 0);  // h2 -> bufA

    k_lin3pool<<<NN / 16, 256>>>(bat, W3, b3);
    k_final<<<(NG * 16 + 255) / 256, 256>>>(out);
}